// round 3
// baseline (speedup 1.0000x reference)
#include <cuda_runtime.h>
#include <cstdint>

#define N_CATS 8
#define NBLOCKS 1184
#define NTHREADS 256

// Device-global scratch: 8x8 confusion-matrix counts + arrival ticket.
// Zero-initialized at module load; reset in-kernel by the finalizing block
// so every graph replay starts clean.
__device__ unsigned int g_cm[64];
__device__ unsigned int g_done;

__global__ __launch_bounds__(NTHREADS) void qwk_fused_kernel(
    const float4* __restrict__ logits4,   // 2 float4 per element
    const int* __restrict__ targets,      // int32
    float* __restrict__ out,
    int n_pairs)                          // n_elems / 2
{
    __shared__ unsigned int s_cm[64];
    __shared__ bool s_is_last;
    int tid = threadIdx.x;
    if (tid < 64) s_cm[tid] = 0u;
    __syncthreads();

    const int2* targets2 = (const int2*)targets;
    int stride = gridDim.x * blockDim.x;

    for (int j = blockIdx.x * blockDim.x + tid; j < n_pairs; j += stride) {
        // Front-batched loads: 4x float4 + 1x int2 (MLP ~5)
        float4 a0 = logits4[4 * j + 0];
        float4 b0 = logits4[4 * j + 1];
        float4 a1 = logits4[4 * j + 2];
        float4 b1 = logits4[4 * j + 3];
        int2 tv2 = targets2[j];

        // argmax elem 0 (first-max-wins, strict >)
        int best0 = 0; float m0 = a0.x;
        if (a0.y > m0) { m0 = a0.y; best0 = 1; }
        if (a0.z > m0) { m0 = a0.z; best0 = 2; }
        if (a0.w > m0) { m0 = a0.w; best0 = 3; }
        if (b0.x > m0) { m0 = b0.x; best0 = 4; }
        if (b0.y > m0) { m0 = b0.y; best0 = 5; }
        if (b0.z > m0) { m0 = b0.z; best0 = 6; }
        if (b0.w > m0) { m0 = b0.w; best0 = 7; }

        // argmax elem 1
        int best1 = 0; float m1 = a1.x;
        if (a1.y > m1) { m1 = a1.y; best1 = 1; }
        if (a1.z > m1) { m1 = a1.z; best1 = 2; }
        if (a1.w > m1) { m1 = a1.w; best1 = 3; }
        if (b1.x > m1) { m1 = b1.x; best1 = 4; }
        if (b1.y > m1) { m1 = b1.y; best1 = 5; }
        if (b1.z > m1) { m1 = b1.z; best1 = 6; }
        if (b1.w > m1) { m1 = b1.w; best1 = 7; }

        if (tv2.x > 0 && tv2.x < N_CATS)
            atomicAdd(&s_cm[tv2.x * N_CATS + best0], 1u);
        if (tv2.y > 0 && tv2.y < N_CATS)
            atomicAdd(&s_cm[tv2.y * N_CATS + best1], 1u);
    }
    __syncthreads();

    // Flush block histogram to global.
    if (tid < 64) {
        unsigned int c = s_cm[tid];
        if (c) atomicAdd(&g_cm[tid], c);
    }

    // Ticket: last block to arrive does the finalize.
    __threadfence();
    __syncthreads();
    if (tid == 0) {
        unsigned int rank = atomicAdd(&g_done, 1u);
        s_is_last = (rank == gridDim.x - 1);
    }
    __syncthreads();
    if (!s_is_last) return;

    if (tid == 0) {
        __threadfence();  // acquire: see all blocks' g_cm atomics

        float cm[64];
        float n = 0.0f;
        #pragma unroll
        for (int i = 0; i < 64; i++) {
            unsigned int c = atomicAdd(&g_cm[i], 0u);   // coherent read
            cm[i] = (float)c;
            n += cm[i];
        }

        float loss;
        if (n == 0.0f) {
            loss = 0.0f;   // qwk = 1 -> loss 0
        } else {
            float inv_n = 1.0f / n;
            #pragma unroll
            for (int i = 0; i < 64; i++) cm[i] *= inv_n;

            float mt[8], mp[8];
            #pragma unroll
            for (int i = 0; i < 8; i++) { mt[i] = 0.0f; mp[i] = 0.0f; }
            #pragma unroll
            for (int i = 0; i < 8; i++)
                #pragma unroll
                for (int jj = 0; jj < 8; jj++) {
                    mt[i] += cm[i * 8 + jj];
                    mp[jj] += cm[i * 8 + jj];
                }

            const float inv_d2 = 1.0f / 49.0f;
            float num = 0.0f, den = 0.0f;
            #pragma unroll
            for (int i = 0; i < 8; i++)
                #pragma unroll
                for (int jj = 0; jj < 8; jj++) {
                    float d = (float)(i - jj);
                    float w = 1.0f - d * d * inv_d2;
                    num += w * cm[i * 8 + jj];
                    den += w * mt[i] * mp[jj];
                }

            float qwk = (den == 0.0f) ? 0.0f : (num / den);
            loss = 1.0f - qwk;
        }
        out[0] = loss;

        // Reset scratch for the next graph replay.
        #pragma unroll
        for (int i = 0; i < 64; i++) g_cm[i] = 0u;
        g_done = 0u;
        __threadfence();
    }
}

extern "C" void kernel_launch(void* const* d_in, const int* in_sizes, int n_in,
                              void* d_out, int out_size) {
    const float4* logits4 = (const float4*)d_in[0];
    const int* targets = (const int*)d_in[1];
    float* out = (float*)d_out;
    int n_elems = in_sizes[1];       // B*S = 2048*4096 (even)
    int n_pairs = n_elems >> 1;

    qwk_fused_kernel<<<NBLOCKS, NTHREADS>>>(logits4, targets, out, n_pairs);
}

// round 4
// speedup vs baseline: 1.0762x; 1.0762x over previous
#include <cuda_runtime.h>
#include <cstdint>

#define N_CATS 8
#define NBLOCKS 592            // 4 CTAs/SM * 148 SMs = one persistent wave
#define NTHREADS 256

// Device-global scratch: 8x8 confusion-matrix counts + arrival ticket.
// Zero at load; finalizing block resets them so every graph replay is clean.
__device__ unsigned int g_cm[64];
__device__ unsigned int g_done;

__global__ __launch_bounds__(NTHREADS, 4) void qwk_fused_kernel(
    const float4* __restrict__ logits4,   // 2 float4 per element
    const int* __restrict__ targets,      // int32
    float* __restrict__ out,
    int n_pairs)                          // n_elems / 2
{
    __shared__ unsigned int s_cm[64];
    __shared__ bool s_is_last;
    int tid = threadIdx.x;
    if (tid < 64) s_cm[tid] = 0u;
    __syncthreads();

    const int2* targets2 = (const int2*)targets;
    int stride = gridDim.x * blockDim.x;

    for (int j = blockIdx.x * blockDim.x + tid; j < n_pairs; j += stride) {
        // Front-batched streaming loads: 4x float4 + 1x int2
        float4 a0 = __ldcs(&logits4[4 * j + 0]);
        float4 b0 = __ldcs(&logits4[4 * j + 1]);
        float4 a1 = __ldcs(&logits4[4 * j + 2]);
        float4 b1 = __ldcs(&logits4[4 * j + 3]);
        int2 tv2 = __ldcs(&targets2[j]);

        // argmax elem 0 (first-max-wins, strict >)
        int best0 = 0; float m0 = a0.x;
        if (a0.y > m0) { m0 = a0.y; best0 = 1; }
        if (a0.z > m0) { m0 = a0.z; best0 = 2; }
        if (a0.w > m0) { m0 = a0.w; best0 = 3; }
        if (b0.x > m0) { m0 = b0.x; best0 = 4; }
        if (b0.y > m0) { m0 = b0.y; best0 = 5; }
        if (b0.z > m0) { m0 = b0.z; best0 = 6; }
        if (b0.w > m0) { m0 = b0.w; best0 = 7; }

        // argmax elem 1
        int best1 = 0; float m1 = a1.x;
        if (a1.y > m1) { m1 = a1.y; best1 = 1; }
        if (a1.z > m1) { m1 = a1.z; best1 = 2; }
        if (a1.w > m1) { m1 = a1.w; best1 = 3; }
        if (b1.x > m1) { m1 = b1.x; best1 = 4; }
        if (b1.y > m1) { m1 = b1.y; best1 = 5; }
        if (b1.z > m1) { m1 = b1.z; best1 = 6; }
        if (b1.w > m1) { m1 = b1.w; best1 = 7; }

        if ((unsigned)(tv2.x - 1) < (unsigned)(N_CATS - 1))
            atomicAdd(&s_cm[tv2.x * N_CATS + best0], 1u);
        if ((unsigned)(tv2.y - 1) < (unsigned)(N_CATS - 1))
            atomicAdd(&s_cm[tv2.y * N_CATS + best1], 1u);
    }
    __syncthreads();

    // Flush block histogram to global.
    if (tid < 64) {
        unsigned int c = s_cm[tid];
        if (c) atomicAdd(&g_cm[tid], c);
    }

    // Ticket: last block to arrive finalizes.
    __threadfence();
    __syncthreads();
    if (tid == 0) {
        unsigned int rank = atomicAdd(&g_done, 1u);
        s_is_last = (rank == gridDim.x - 1);
    }
    __syncthreads();
    if (!s_is_last) return;

    if (tid == 0) {
        __threadfence();  // acquire: see all blocks' g_cm atomics

        float cm[64];
        float n = 0.0f;
        #pragma unroll
        for (int i = 0; i < 64; i++) {
            unsigned int c = atomicAdd(&g_cm[i], 0u);   // coherent read
            cm[i] = (float)c;
            n += cm[i];
        }

        float loss;
        if (n == 0.0f) {
            loss = 0.0f;   // qwk = 1 -> loss 0
        } else {
            float inv_n = 1.0f / n;
            #pragma unroll
            for (int i = 0; i < 64; i++) cm[i] *= inv_n;

            float mt[8], mp[8];
            #pragma unroll
            for (int i = 0; i < 8; i++) { mt[i] = 0.0f; mp[i] = 0.0f; }
            #pragma unroll
            for (int i = 0; i < 8; i++)
                #pragma unroll
                for (int jj = 0; jj < 8; jj++) {
                    mt[i] += cm[i * 8 + jj];
                    mp[jj] += cm[i * 8 + jj];
                }

            const float inv_d2 = 1.0f / 49.0f;
            float num = 0.0f, den = 0.0f;
            #pragma unroll
            for (int i = 0; i < 8; i++)
                #pragma unroll
                for (int jj = 0; jj < 8; jj++) {
                    float d = (float)(i - jj);
                    float w = 1.0f - d * d * inv_d2;
                    num += w * cm[i * 8 + jj];
                    den += w * mt[i] * mp[jj];
                }

            float qwk = (den == 0.0f) ? 0.0f : (num / den);
            loss = 1.0f - qwk;
        }
        out[0] = loss;

        // Reset scratch for the next graph replay.
        #pragma unroll
        for (int i = 0; i < 64; i++) g_cm[i] = 0u;
        g_done = 0u;
        __threadfence();
    }
}

extern "C" void kernel_launch(void* const* d_in, const int* in_sizes, int n_in,
                              void* d_out, int out_size) {
    const float4* logits4 = (const float4*)d_in[0];
    const int* targets = (const int*)d_in[1];
    float* out = (float*)d_out;
    int n_elems = in_sizes[1];       // B*S = 2048*4096 (even)
    int n_pairs = n_elems >> 1;

    qwk_fused_kernel<<<NBLOCKS, NTHREADS>>>(logits4, targets, out, n_pairs);
}